// round 7
// baseline (speedup 1.0000x reference)
#include <cuda_runtime.h>

#define N_TOTAL 65536
#define NNZ (16 * N_TOTAL)
#define STEPS 16
#define MAXW 64
#define TB 256
#define PARTS 4
#define ROWS_PER_BLK (TB / PARTS)        // 64 rows per block
#define GRID (N_TOTAL / ROWS_PER_BLK)    // 1024 blocks (single wave, 7/SM max)

// ---------------------------------------------------------------------------
// Device-global scratch (allocation-free).
__device__ float2   g_U[2][N_TOTAL];            // interleaved (Ur,Ui) ping-pong
__device__ unsigned g_cnt[N_TOTAL];             // per-row nnz count / fill cursor
__device__ int2     g_pairs[MAXW * N_TOTAL];    // ELL slot-major: [slot*N + row]
__device__ unsigned g_bar;                      // grid barrier counter

// ---------------------------------------------------------------------------
// K1: zero counts & barrier, pack U0 into interleaved float2.
__global__ void init_kernel(const float* __restrict__ Ur0,
                            const float* __restrict__ Ui0) {
    int i = blockIdx.x * blockDim.x + threadIdx.x;
    if (i < N_TOTAL) {
        g_cnt[i] = 0;
        g_U[0][i] = make_float2(Ur0[i], Ui0[i]);
    }
    if (i == 0) g_bar = 0;
}

// K2: single-pass ELL fill; slot position comes straight from the atomic.
__global__ __launch_bounds__(TB)
void fill_kernel(const float4* __restrict__ A4,
                 const int4* __restrict__ R4,
                 const int4* __restrict__ C4, float dz) {
    int i = blockIdx.x * blockDim.x + threadIdx.x;
    if (i >= NNZ / 4) return;
    float4 a = A4[i];
    int4   r = R4[i];
    int4   c = C4[i];
    unsigned p0 = atomicAdd(&g_cnt[r.x], 1u);
    unsigned p1 = atomicAdd(&g_cnt[r.y], 1u);
    unsigned p2 = atomicAdd(&g_cnt[r.z], 1u);
    unsigned p3 = atomicAdd(&g_cnt[r.w], 1u);
    g_pairs[p0 * N_TOTAL + r.x] = make_int2(c.x, __float_as_int(a.x * dz));
    g_pairs[p1 * N_TOTAL + r.y] = make_int2(c.y, __float_as_int(a.y * dz));
    g_pairs[p2 * N_TOTAL + r.z] = make_int2(c.z, __float_as_int(a.z * dz));
    g_pairs[p3 * N_TOTAL + r.w] = make_int2(c.w, __float_as_int(a.w * dz));
}

// ---------------------------------------------------------------------------
// Grid barrier, CG-style: leader releases, arrives, polls, acquires; block
// syncs around it. Single-wave launch guarantees no deadlock.
__device__ __forceinline__ void grid_bar(int round) {
    __syncthreads();
    if (threadIdx.x == 0) {
        __threadfence();                              // release my block's writes
        atomicAdd(&g_bar, 1u);
        const unsigned target = (unsigned)(round + 1) * GRID;
        while (*(volatile unsigned*)&g_bar < target) { __nanosleep(64); }
        __threadfence();                              // acquire peers' writes
    }
    __syncthreads();
}

// ---------------------------------------------------------------------------
// K3: persistent stepper. Pairs (immutable) load through L1 and stay resident
// across all 16 steps; state U goes through __ldcg (L2-only: coherent across
// SMs within the launch, and doesn't evict pairs from L1).
__global__ __launch_bounds__(TB, 7)
void persist_kernel(float* __restrict__ out) {
    __shared__ float s_r[PARTS][ROWS_PER_BLK];
    __shared__ float s_i[PARTS][ROWS_PER_BLK];

    const int part = threadIdx.x >> 6;               // 0..3
    const int lr   = threadIdx.x & (ROWS_PER_BLK - 1);
    const int r    = blockIdx.x * ROWS_PER_BLK + lr;
    const unsigned cnt = g_cnt[r];

    int src = 0;
    for (int s = 0; s < STEPS; s++) {
        const float2* __restrict__ U = g_U[src];
        float sr = 0.f, si = 0.f;
        #pragma unroll 4
        for (unsigned j = part; j < cnt; j += PARTS) {
            int2 p = g_pairs[j * N_TOTAL + r];       // L1-resident after step 1
            float2 u = __ldcg(&U[p.x]);              // L2-only (coherent)
            float v = __int_as_float(p.y);
            sr = fmaf(v, u.y, sr);                   // dz*(A@Ui)[r]
            si = fmaf(v, u.x, si);                   // dz*(A@Ur)[r]
        }
        s_r[part][lr] = sr;
        s_i[part][lr] = si;
        __syncthreads();

        if (part == 0) {
            float tr = s_r[0][lr] + s_r[1][lr] + s_r[2][lr] + s_r[3][lr];
            float ti = s_i[0][lr] + s_i[1][lr] + s_i[2][lr] + s_i[3][lr];
            float2 mine = __ldcg(&U[r]);
            float2 nxt = make_float2(mine.x - tr, mine.y + ti);
            g_U[src ^ 1][r] = nxt;
            if (s == STEPS - 1) {
                out[r]           = nxt.x;
                out[N_TOTAL + r] = nxt.y;
            }
        }
        src ^= 1;
        if (s != STEPS - 1) grid_bar(s);
    }
}

// ---------------------------------------------------------------------------
extern "C" void kernel_launch(void* const* d_in, const int* in_sizes, int n_in,
                              void* d_out, int out_size) {
    const float* A_vals  = (const float*)d_in[0];
    const int*   row_idx = (const int*)d_in[1];
    const int*   col_idx = (const int*)d_in[2];
    const float* Ur0     = (const float*)d_in[3];
    const float* Ui0     = (const float*)d_in[4];
    const float dz = 1.0f / (float)STEPS;

    init_kernel<<<(N_TOTAL + TB - 1) / TB, TB>>>(Ur0, Ui0);
    fill_kernel<<<(NNZ / 4 + TB - 1) / TB, TB>>>(
        (const float4*)A_vals, (const int4*)row_idx, (const int4*)col_idx, dz);
    persist_kernel<<<GRID, TB>>>((float*)d_out);
}

// round 8
// speedup vs baseline: 1.2538x; 1.2538x over previous
#include <cuda_runtime.h>

#define N_TOTAL 65536
#define NNZ (16 * N_TOTAL)
#define STEPS 16
#define MAXW 64
#define TB 256
#define PARTS 8
#define ROWS_PER_BLK (TB / PARTS)   // 32 rows per block

// ---------------------------------------------------------------------------
// Device-global scratch (allocation-free).
__device__ float2   g_U[2][N_TOTAL];            // interleaved (Ur,Ui) ping-pong
__device__ unsigned g_cnt[N_TOTAL];             // per-row nnz count / fill cursor
__device__ int2     g_pairs[MAXW * N_TOTAL];    // ELL slot-major: [slot*N + row]

// ---------------------------------------------------------------------------
// K1: zero counts, pack U0 into interleaved float2.
__global__ void init_kernel(const float* __restrict__ Ur0,
                            const float* __restrict__ Ui0) {
    int i = blockIdx.x * blockDim.x + threadIdx.x;
    if (i < N_TOTAL) {
        g_cnt[i] = 0;
        g_U[0][i] = make_float2(Ur0[i], Ui0[i]);
    }
}

// K2: single-pass ELL fill, 8 nnz per thread for deep MLP on the
// atomic->scattered-store chains.
__global__ __launch_bounds__(TB)
void fill_kernel(const float4* __restrict__ A4,
                 const int4* __restrict__ R4,
                 const int4* __restrict__ C4, float dz) {
    int i = blockIdx.x * blockDim.x + threadIdx.x;   // over NNZ/8
    if (i >= NNZ / 8) return;
    float4 a0 = A4[2 * i], a1 = A4[2 * i + 1];
    int4   r0 = R4[2 * i], r1 = R4[2 * i + 1];
    int4   c0 = C4[2 * i], c1 = C4[2 * i + 1];
    unsigned p0 = atomicAdd(&g_cnt[r0.x], 1u);
    unsigned p1 = atomicAdd(&g_cnt[r0.y], 1u);
    unsigned p2 = atomicAdd(&g_cnt[r0.z], 1u);
    unsigned p3 = atomicAdd(&g_cnt[r0.w], 1u);
    unsigned p4 = atomicAdd(&g_cnt[r1.x], 1u);
    unsigned p5 = atomicAdd(&g_cnt[r1.y], 1u);
    unsigned p6 = atomicAdd(&g_cnt[r1.z], 1u);
    unsigned p7 = atomicAdd(&g_cnt[r1.w], 1u);
    g_pairs[p0 * N_TOTAL + r0.x] = make_int2(c0.x, __float_as_int(a0.x * dz));
    g_pairs[p1 * N_TOTAL + r0.y] = make_int2(c0.y, __float_as_int(a0.y * dz));
    g_pairs[p2 * N_TOTAL + r0.z] = make_int2(c0.z, __float_as_int(a0.z * dz));
    g_pairs[p3 * N_TOTAL + r0.w] = make_int2(c0.w, __float_as_int(a0.w * dz));
    g_pairs[p4 * N_TOTAL + r1.x] = make_int2(c1.x, __float_as_int(a1.x * dz));
    g_pairs[p5 * N_TOTAL + r1.y] = make_int2(c1.y, __float_as_int(a1.y * dz));
    g_pairs[p6 * N_TOTAL + r1.z] = make_int2(c1.z, __float_as_int(a1.z * dz));
    g_pairs[p7 * N_TOTAL + r1.w] = make_int2(c1.w, __float_as_int(a1.w * dz));
}

// ---------------------------------------------------------------------------
// K3: one Euler step, 8 lanes per row. part = tid>>5, so each warp covers 32
// consecutive rows at one part -> slot-major pair loads stay fully coalesced.
// Partials reduced via smem; part 0 writes the ping-pong (and final output).
template <bool FINAL>
__global__ __launch_bounds__(TB)
void step_kernel(int src, float* __restrict__ out) {
    __shared__ float s_r[PARTS][ROWS_PER_BLK];
    __shared__ float s_i[PARTS][ROWS_PER_BLK];

    const int part = threadIdx.x >> 5;               // 0..7 (= warp id)
    const int lr   = threadIdx.x & (ROWS_PER_BLK - 1);
    const int r    = blockIdx.x * ROWS_PER_BLK + lr;

    const float2* __restrict__ U = g_U[src];
    const unsigned cnt = g_cnt[r];

    float sr = 0.f, si = 0.f;
    #pragma unroll 2
    for (unsigned j = part; j < cnt; j += PARTS) {
        int2 p = g_pairs[j * N_TOTAL + r];
        float2 u = __ldg(&U[p.x]);
        float v = __int_as_float(p.y);
        sr = fmaf(v, u.y, sr);                       // dz*(A@Ui)[r]
        si = fmaf(v, u.x, si);                       // dz*(A@Ur)[r]
    }
    s_r[part][lr] = sr;
    s_i[part][lr] = si;
    __syncthreads();

    if (part == 0) {
        float tr = 0.f, ti = 0.f;
        #pragma unroll
        for (int k = 0; k < PARTS; k++) { tr += s_r[k][lr]; ti += s_i[k][lr]; }
        float2 mine = U[r];
        float2 nxt = make_float2(mine.x - tr, mine.y + ti);
        g_U[src ^ 1][r] = nxt;
        if (FINAL) {
            out[r]           = nxt.x;
            out[N_TOTAL + r] = nxt.y;
        }
    }
}

// ---------------------------------------------------------------------------
extern "C" void kernel_launch(void* const* d_in, const int* in_sizes, int n_in,
                              void* d_out, int out_size) {
    const float* A_vals  = (const float*)d_in[0];
    const int*   row_idx = (const int*)d_in[1];
    const int*   col_idx = (const int*)d_in[2];
    const float* Ur0     = (const float*)d_in[3];
    const float* Ui0     = (const float*)d_in[4];
    const float dz = 1.0f / (float)STEPS;

    init_kernel<<<(N_TOTAL + TB - 1) / TB, TB>>>(Ur0, Ui0);
    fill_kernel<<<(NNZ / 8 + TB - 1) / TB, TB>>>(
        (const float4*)A_vals, (const int4*)row_idx, (const int4*)col_idx, dz);

    const int grid = N_TOTAL / ROWS_PER_BLK;         // 2048 blocks
    int src = 0;
    for (int s = 0; s < STEPS - 1; s++) {
        step_kernel<false><<<grid, TB>>>(src, nullptr);
        src ^= 1;
    }
    step_kernel<true><<<grid, TB>>>(src, (float*)d_out);
}

// round 9
// speedup vs baseline: 1.4799x; 1.1803x over previous
#include <cuda_runtime.h>
#include <cuda_fp16.h>

#define N_TOTAL 65536
#define NNZ (16 * N_TOTAL)
#define STEPS 16
#define MAXW 64
#define NGROUP (MAXW / 4)           // 16 uint4 groups per row
#define TB 256
#define PARTS 4
#define ROWS_PER_BLK (TB / PARTS)   // 64 rows per block

// ---------------------------------------------------------------------------
// Device-global scratch (allocation-free).
__device__ float2   g_U[2][N_TOTAL];          // interleaved (Ur,Ui) ping-pong
__device__ unsigned g_cnt[N_TOTAL];           // per-row nnz count / fill cursor
__device__ uint4    g_q4[NGROUP * N_TOTAL];   // packed ELL: [slot_group][row],
                                              // each u32 = {f16 val, u16 col}

// ---------------------------------------------------------------------------
// K1: zero counts, pack U0 into interleaved float2.
__global__ void init_kernel(const float* __restrict__ Ur0,
                            const float* __restrict__ Ui0) {
    int i = blockIdx.x * blockDim.x + threadIdx.x;
    if (i < N_TOTAL) {
        g_cnt[i] = 0;
        g_U[0][i] = make_float2(Ur0[i], Ui0[i]);
    }
}

// ---------------------------------------------------------------------------
// K2: single-pass packed-ELL fill, 8 nnz per thread for MLP.
__device__ __forceinline__ void put(int r, int c, float av) {
    unsigned pos = atomicAdd(&g_cnt[r], 1u);
    unsigned packed = (unsigned)(c & 0xFFFF)
                    | ((unsigned)__half_as_ushort(__float2half_rn(av)) << 16);
    // uint element index inside g_q4 viewed as u32[]:
    ((unsigned*)g_q4)[(((pos >> 2) * N_TOTAL + (unsigned)r) << 2) + (pos & 3)] = packed;
}

__global__ __launch_bounds__(TB)
void fill_kernel(const float4* __restrict__ A4,
                 const int4* __restrict__ R4,
                 const int4* __restrict__ C4, float dz) {
    int i = blockIdx.x * blockDim.x + threadIdx.x;   // over NNZ/8
    if (i >= NNZ / 8) return;
    float4 a0 = A4[2 * i], a1 = A4[2 * i + 1];
    int4   r0 = R4[2 * i], r1 = R4[2 * i + 1];
    int4   c0 = C4[2 * i], c1 = C4[2 * i + 1];
    put(r0.x, c0.x, a0.x * dz);
    put(r0.y, c0.y, a0.y * dz);
    put(r0.z, c0.z, a0.z * dz);
    put(r0.w, c0.w, a0.w * dz);
    put(r1.x, c1.x, a1.x * dz);
    put(r1.y, c1.y, a1.y * dz);
    put(r1.z, c1.z, a1.z * dz);
    put(r1.w, c1.w, a1.w * dz);
}

// ---------------------------------------------------------------------------
// K3: one Euler step. 4 lanes per row; lane `part` handles slot-groups
// part, part+4, ... Each iteration: ONE coalesced 16B load (4 packed nnz)
// then 4 independent gathers. Tail slots masked by cnt (garbage cols are
// u16 -> always in-bounds; vals forced to 0).
template <bool FINAL>
__global__ __launch_bounds__(TB)
void step_kernel(int src, float* __restrict__ out) {
    __shared__ float s_r[PARTS][ROWS_PER_BLK];
    __shared__ float s_i[PARTS][ROWS_PER_BLK];

    const int part = threadIdx.x >> 6;               // 0..3
    const int lr   = threadIdx.x & (ROWS_PER_BLK - 1);
    const int r    = blockIdx.x * ROWS_PER_BLK + lr;

    const float2* __restrict__ U = g_U[src];
    const unsigned cnt = g_cnt[r];

    float sr = 0.f, si = 0.f;
    for (unsigned g = part; 4 * g < cnt; g += PARTS) {
        uint4 q = g_q4[g * N_TOTAL + r];
        unsigned b = 4 * g;
        float2 u0 = __ldg(&U[q.x & 0xFFFFu]);
        float2 u1 = __ldg(&U[q.y & 0xFFFFu]);
        float2 u2 = __ldg(&U[q.z & 0xFFFFu]);
        float2 u3 = __ldg(&U[q.w & 0xFFFFu]);
        float v0 = (b + 0 < cnt) ? __half2float(__ushort_as_half((unsigned short)(q.x >> 16))) : 0.f;
        float v1 = (b + 1 < cnt) ? __half2float(__ushort_as_half((unsigned short)(q.y >> 16))) : 0.f;
        float v2 = (b + 2 < cnt) ? __half2float(__ushort_as_half((unsigned short)(q.z >> 16))) : 0.f;
        float v3 = (b + 3 < cnt) ? __half2float(__ushort_as_half((unsigned short)(q.w >> 16))) : 0.f;
        sr = fmaf(v0, u0.y, sr);  si = fmaf(v0, u0.x, si);
        sr = fmaf(v1, u1.y, sr);  si = fmaf(v1, u1.x, si);
        sr = fmaf(v2, u2.y, sr);  si = fmaf(v2, u2.x, si);
        sr = fmaf(v3, u3.y, sr);  si = fmaf(v3, u3.x, si);
    }
    s_r[part][lr] = sr;
    s_i[part][lr] = si;
    __syncthreads();

    if (part == 0) {
        float tr = s_r[0][lr] + s_r[1][lr] + s_r[2][lr] + s_r[3][lr];
        float ti = s_i[0][lr] + s_i[1][lr] + s_i[2][lr] + s_i[3][lr];
        float2 mine = U[r];
        float2 nxt = make_float2(mine.x - tr, mine.y + ti);
        g_U[src ^ 1][r] = nxt;
        if (FINAL) {
            out[r]           = nxt.x;
            out[N_TOTAL + r] = nxt.y;
        }
    }
}

// ---------------------------------------------------------------------------
extern "C" void kernel_launch(void* const* d_in, const int* in_sizes, int n_in,
                              void* d_out, int out_size) {
    const float* A_vals  = (const float*)d_in[0];
    const int*   row_idx = (const int*)d_in[1];
    const int*   col_idx = (const int*)d_in[2];
    const float* Ur0     = (const float*)d_in[3];
    const float* Ui0     = (const float*)d_in[4];
    const float dz = 1.0f / (float)STEPS;

    init_kernel<<<(N_TOTAL + TB - 1) / TB, TB>>>(Ur0, Ui0);
    fill_kernel<<<(NNZ / 8 + TB - 1) / TB, TB>>>(
        (const float4*)A_vals, (const int4*)row_idx, (const int4*)col_idx, dz);

    const int grid = N_TOTAL / ROWS_PER_BLK;         // 1024 blocks
    int src = 0;
    for (int s = 0; s < STEPS - 1; s++) {
        step_kernel<false><<<grid, TB>>>(src, nullptr);
        src ^= 1;
    }
    step_kernel<true><<<grid, TB>>>(src, (float*)d_out);
}